// round 1
// baseline (speedup 1.0000x reference)
#include <cuda_runtime.h>

#define B_TOTAL 131072
#define T_STEPS 8
#define NB 4
#define WARPS 8
#define BPB (NB * WARPS)           // 32 batches per block
#define NBLK (B_TOTAL / BPB)       // 4096 blocks

// Layer-1 output sequence scratch: [B][T][64] fp32 = 256 MB
__device__ float g_h1[B_TOTAL * T_STEPS * 64];

__device__ __forceinline__ float sigf(float x) {
    return __fdividef(1.0f, 1.0f + __expf(-x));
}
__device__ __forceinline__ float tanh_f(float x) {
    // tanh(x) = 2*sigmoid(2x) - 1 ; __expf(inf) saturates correctly
    return 2.0f * __fdividef(1.0f, 1.0f + __expf(-2.0f * x)) - 1.0f;
}

// Shared-mem float sizes
// pass1: sWih 1536 | sWhh 16384 | sBias 256 | sH 2048 | sX 1536  -> 21760 floats (87040 B)
// pass2: sW 32768 | sBias 256 | sIn 4096                          -> 37120 floats (148480 B)
#define SMEM1_BYTES (21760 * 4)
#define SMEM2_BYTES (37120 * 4)

__global__ void __launch_bounds__(256) lstm_pass1(
    const float* __restrict__ x,
    const float* __restrict__ Wih, const float* __restrict__ Whh,
    const float* __restrict__ bih, const float* __restrict__ bhh)
{
    extern __shared__ float sm[];
    float* sWih  = sm;                 // [i(6)][j(64)][gate(4)]
    float* sWhh  = sWih + 1536;        // [k(64)][j(64)][gate(4)]
    float* sBias = sWhh + 16384;       // [j(64)][gate(4)]
    float* sH    = sBias + 256;        // [warp(8)][nb(4)][64]
    float* sX    = sH + 2048;          // [nb_lin(32)][48]

    const int tid = threadIdx.x;

    for (int idx = tid; idx < 1536; idx += 256) {
        int r = idx / 6, i = idx - r * 6;
        int gate = r >> 6, j = r & 63;
        sWih[(i * 64 + j) * 4 + gate] = Wih[idx];
    }
    for (int idx = tid; idx < 16384; idx += 256) {
        int r = idx >> 6, k = idx & 63;
        int gate = r >> 6, j = r & 63;
        sWhh[(k * 64 + j) * 4 + gate] = Whh[idx];
    }
    {
        int idx = tid;
        if (idx < 256) {
            int gate = idx >> 6, j = idx & 63;
            sBias[j * 4 + gate] = bih[idx] + bhh[idx];
        }
    }
    for (int idx = tid; idx < 2048; idx += 256) sH[idx] = 0.0f;

    const int base = blockIdx.x * BPB;
    for (int idx = tid; idx < BPB * 48; idx += 256) {
        int nbl = idx / 48, rem = idx - nbl * 48;
        sX[idx] = x[(base + nbl) * 48 + rem];  // x is [B][8][6] contiguous
    }
    __syncthreads();

    const int w = tid >> 5, lane = tid & 31;
    float* myH = sH + w * NB * 64;
    const float* myX = sX + w * NB * 48;

    float ca[NB], cb[NB], ha[NB], hb[NB];
#pragma unroll
    for (int nb = 0; nb < NB; nb++) { ca[nb] = cb[nb] = ha[nb] = hb[nb] = 0.0f; }

    const float4* W4  = (const float4*)sWhh;
    const float4* Wx4 = (const float4*)sWih;
    const float4  bj  = ((const float4*)sBias)[lane];
    const float4  bj2 = ((const float4*)sBias)[lane + 32];

    for (int t = 0; t < T_STEPS; t++) {
        float4 pa[NB], pb[NB];
#pragma unroll
        for (int nb = 0; nb < NB; nb++) { pa[nb] = bj; pb[nb] = bj2; }

#pragma unroll
        for (int i = 0; i < 6; i++) {
            float4 wa = Wx4[i * 64 + lane];
            float4 wb = Wx4[i * 64 + lane + 32];
#pragma unroll
            for (int nb = 0; nb < NB; nb++) {
                float v = myX[nb * 48 + t * 6 + i];
                pa[nb].x += v * wa.x; pa[nb].y += v * wa.y;
                pa[nb].z += v * wa.z; pa[nb].w += v * wa.w;
                pb[nb].x += v * wb.x; pb[nb].y += v * wb.y;
                pb[nb].z += v * wb.z; pb[nb].w += v * wb.w;
            }
        }

#pragma unroll 16
        for (int k = 0; k < 64; k++) {
            float4 wa = W4[k * 64 + lane];
            float4 wb = W4[k * 64 + lane + 32];
#pragma unroll
            for (int nb = 0; nb < NB; nb++) {
                float v = myH[nb * 64 + k];
                pa[nb].x += v * wa.x; pa[nb].y += v * wa.y;
                pa[nb].z += v * wa.z; pa[nb].w += v * wa.w;
                pb[nb].x += v * wb.x; pb[nb].y += v * wb.y;
                pb[nb].z += v * wb.z; pb[nb].w += v * wb.w;
            }
        }

        __syncwarp();
#pragma unroll
        for (int nb = 0; nb < NB; nb++) {
            float ig = sigf(pa[nb].x), fg = sigf(pa[nb].y);
            float gg = tanh_f(pa[nb].z), og = sigf(pa[nb].w);
            ca[nb] = fg * ca[nb] + ig * gg;
            ha[nb] = og * tanh_f(ca[nb]);

            ig = sigf(pb[nb].x); fg = sigf(pb[nb].y);
            gg = tanh_f(pb[nb].z); og = sigf(pb[nb].w);
            cb[nb] = fg * cb[nb] + ig * gg;
            hb[nb] = og * tanh_f(cb[nb]);

            myH[nb * 64 + lane]      = ha[nb];
            myH[nb * 64 + lane + 32] = hb[nb];

            int b = base + w * NB + nb;
            g_h1[(b * T_STEPS + t) * 64 + lane]      = ha[nb];
            g_h1[(b * T_STEPS + t) * 64 + lane + 32] = hb[nb];
        }
        __syncwarp();
    }
}

__global__ void __launch_bounds__(256) lstm_pass2(
    const float* __restrict__ Wih, const float* __restrict__ Whh,
    const float* __restrict__ bih, const float* __restrict__ bhh,
    const float* __restrict__ Wfc, const float* __restrict__ bfc,
    float* __restrict__ out)
{
    extern __shared__ float sm[];
    float* sW    = sm;            // [kk(128)][j(64)][gate(4)]  kk<64: Wih1, kk>=64: Whh1
    float* sBias = sW + 32768;    // [j(64)][gate(4)]
    float* sIn   = sBias + 256;   // [warp(8)][nb(4)][128]  (0..63 input, 64..127 h)

    const int tid = threadIdx.x;

    for (int idx = tid; idx < 16384; idx += 256) {
        int r = idx >> 6, k = idx & 63;
        int gate = r >> 6, j = r & 63;
        sW[(k * 64 + j) * 4 + gate]        = Wih[idx];
        sW[((k + 64) * 64 + j) * 4 + gate] = Whh[idx];
    }
    {
        int idx = tid;
        if (idx < 256) {
            int gate = idx >> 6, j = idx & 63;
            sBias[j * 4 + gate] = bih[idx] + bhh[idx];
        }
    }
    for (int idx = tid; idx < 4096; idx += 256) sIn[idx] = 0.0f;
    __syncthreads();

    const int w = tid >> 5, lane = tid & 31;
    const int base = blockIdx.x * BPB + w * NB;
    float* myIn = sIn + w * NB * 128;

    float ca[NB], cb[NB], ha[NB], hb[NB];
#pragma unroll
    for (int nb = 0; nb < NB; nb++) { ca[nb] = cb[nb] = ha[nb] = hb[nb] = 0.0f; }

    const float4* W4 = (const float4*)sW;
    const float4  bj  = ((const float4*)sBias)[lane];
    const float4  bj2 = ((const float4*)sBias)[lane + 32];
    const float wf1 = Wfc[lane];
    const float wf2 = Wfc[lane + 32];

    for (int t = 0; t < T_STEPS; t++) {
        // stage layer-2 input (layer-1 h at step t)
#pragma unroll
        for (int nb = 0; nb < NB; nb++) {
            const float* src = g_h1 + ((base + nb) * T_STEPS + t) * 64;
            myIn[nb * 128 + lane]      = src[lane];
            myIn[nb * 128 + lane + 32] = src[lane + 32];
        }
        __syncwarp();

        float4 pa[NB], pb[NB];
#pragma unroll
        for (int nb = 0; nb < NB; nb++) { pa[nb] = bj; pb[nb] = bj2; }

#pragma unroll 16
        for (int k = 0; k < 128; k++) {
            float4 wa = W4[k * 64 + lane];
            float4 wb = W4[k * 64 + lane + 32];
#pragma unroll
            for (int nb = 0; nb < NB; nb++) {
                float v = myIn[nb * 128 + k];
                pa[nb].x += v * wa.x; pa[nb].y += v * wa.y;
                pa[nb].z += v * wa.z; pa[nb].w += v * wa.w;
                pb[nb].x += v * wb.x; pb[nb].y += v * wb.y;
                pb[nb].z += v * wb.z; pb[nb].w += v * wb.w;
            }
        }

        __syncwarp();
#pragma unroll
        for (int nb = 0; nb < NB; nb++) {
            float ig = sigf(pa[nb].x), fg = sigf(pa[nb].y);
            float gg = tanh_f(pa[nb].z), og = sigf(pa[nb].w);
            ca[nb] = fg * ca[nb] + ig * gg;
            ha[nb] = og * tanh_f(ca[nb]);

            ig = sigf(pb[nb].x); fg = sigf(pb[nb].y);
            gg = tanh_f(pb[nb].z); og = sigf(pb[nb].w);
            cb[nb] = fg * cb[nb] + ig * gg;
            hb[nb] = og * tanh_f(cb[nb]);

            myIn[nb * 128 + 64 + lane]      = ha[nb];
            myIn[nb * 128 + 64 + lane + 32] = hb[nb];
        }
        __syncwarp();
    }

    // fused FC on final h2
    float p[NB];
#pragma unroll
    for (int nb = 0; nb < NB; nb++) p[nb] = ha[nb] * wf1 + hb[nb] * wf2;
#pragma unroll
    for (int off = 16; off >= 1; off >>= 1) {
#pragma unroll
        for (int nb = 0; nb < NB; nb++)
            p[nb] += __shfl_xor_sync(0xffffffffu, p[nb], off);
    }
    if (lane == 0) {
        float b0 = bfc[0];
#pragma unroll
        for (int nb = 0; nb < NB; nb++) out[base + nb] = p[nb] + b0;
    }
}

extern "C" void kernel_launch(void* const* d_in, const int* in_sizes, int n_in,
                              void* d_out, int out_size)
{
    const float* x    = (const float*)d_in[0];
    const float* Wih0 = (const float*)d_in[1];
    const float* Whh0 = (const float*)d_in[2];
    const float* bih0 = (const float*)d_in[3];
    const float* bhh0 = (const float*)d_in[4];
    const float* Wih1 = (const float*)d_in[5];
    const float* Whh1 = (const float*)d_in[6];
    const float* bih1 = (const float*)d_in[7];
    const float* bhh1 = (const float*)d_in[8];
    const float* Wfc  = (const float*)d_in[9];
    const float* bfc  = (const float*)d_in[10];
    float* out = (float*)d_out;

    cudaFuncSetAttribute(lstm_pass1, cudaFuncAttributeMaxDynamicSharedMemorySize, SMEM1_BYTES);
    cudaFuncSetAttribute(lstm_pass2, cudaFuncAttributeMaxDynamicSharedMemorySize, SMEM2_BYTES);

    lstm_pass1<<<NBLK, 256, SMEM1_BYTES>>>(x, Wih0, Whh0, bih0, bhh0);
    lstm_pass2<<<NBLK, 256, SMEM2_BYTES>>>(Wih1, Whh1, bih1, bhh1, Wfc, bfc, out);
}

// round 2
// speedup vs baseline: 1.3361x; 1.3361x over previous
#include <cuda_runtime.h>

#define B_TOTAL 131072
#define T_STEPS 8
#define NB 8
#define WARPS 8
#define BPB (NB * WARPS)           // 64 batches per block
#define NBLK (B_TOTAL / BPB)       // 2048 blocks

// Layer-1 output scratch, layout [blk][warp][t][k(64)][nb(8)] = 256 MB
__device__ float g_h1[(size_t)NBLK * WARPS * T_STEPS * 64 * NB];

typedef unsigned long long u64t;

__device__ __forceinline__ u64t pk(float x, float y) {
    u64t r; asm("mov.b64 %0, {%1, %2};" : "=l"(r) : "f"(x), "f"(y)); return r;
}
__device__ __forceinline__ void upk(u64t v, float& x, float& y) {
    asm("mov.b64 {%0, %1}, %2;" : "=f"(x), "=f"(y) : "l"(v));
}
__device__ __forceinline__ void fma2(u64t& d, u64t a, u64t b) {
    asm("fma.rn.f32x2 %0, %1, %2, %0;" : "+l"(d) : "l"(a), "l"(b));
}

__device__ __forceinline__ float sigf(float x) {
    return __fdividef(1.0f, 1.0f + __expf(-x));
}
__device__ __forceinline__ float tanh_f(float x) {
    return 2.0f * __fdividef(1.0f, 1.0f + __expf(-2.0f * x)) - 1.0f;
}

// smem float counts
// pass1: sWih[6][64][4]=1536 | sWhh[64][64][4]=16384 | sBias 256 | sH[w][64][8]=4096 | sX[w][48][8]=3072 -> 25344 (101376 B)
// pass2: sW[128][64][4]=32768 | sBias 256 | sIn[w][128][8]=8192 -> 41216 (164864 B)
#define SMEM1_BYTES (25344 * 4)
#define SMEM2_BYTES (41216 * 4)

// one k-slice of the gate GEMM: weights per-lane (2x float4), inputs broadcast (2x float4)
#define K_SLICE(W4PTR, H4PTR, KW, KH)                                          \
    {                                                                           \
        float4 wa = (W4PTR)[(KW) * 64 + lane];                                  \
        float4 wb = (W4PTR)[(KW) * 64 + lane + 32];                             \
        float4 hA = (H4PTR)[(KH) * 2];                                          \
        float4 hB = (H4PTR)[(KH) * 2 + 1];                                      \
        u64t wif1 = pk(wa.x, wa.y), wgo1 = pk(wa.z, wa.w);                      \
        u64t wif2 = pk(wb.x, wb.y), wgo2 = pk(wb.z, wb.w);                      \
        float hv[8] = {hA.x, hA.y, hA.z, hA.w, hB.x, hB.y, hB.z, hB.w};         \
        _Pragma("unroll")                                                       \
        for (int nb = 0; nb < NB; nb++) {                                       \
            u64t vv = pk(hv[nb], hv[nb]);                                       \
            fma2(aif1[nb], vv, wif1);                                           \
            fma2(ago1[nb], vv, wgo1);                                           \
            fma2(aif2[nb], vv, wif2);                                           \
            fma2(ago2[nb], vv, wgo2);                                           \
        }                                                                       \
    }

#define ACT_AND_STATE(nb)                                                       \
    float ha_##nb, hb_##nb;                                                     \
    {                                                                           \
        float gi, gf, gg, go;                                                   \
        upk(aif1[nb], gi, gf); upk(ago1[nb], gg, go);                           \
        float i1 = sigf(gi), f1 = sigf(gf), g1 = tanh_f(gg), o1 = sigf(go);     \
        ca[nb] = f1 * ca[nb] + i1 * g1;                                         \
        ha_##nb = o1 * tanh_f(ca[nb]);                                          \
        upk(aif2[nb], gi, gf); upk(ago2[nb], gg, go);                           \
        float i2 = sigf(gi), f2 = sigf(gf), g2 = tanh_f(gg), o2 = sigf(go);     \
        cb[nb] = f2 * cb[nb] + i2 * g2;                                         \
        hb_##nb = o2 * tanh_f(cb[nb]);                                          \
    }

__global__ void __launch_bounds__(256) lstm_pass1(
    const float* __restrict__ x,
    const float* __restrict__ Wih, const float* __restrict__ Whh,
    const float* __restrict__ bih, const float* __restrict__ bhh)
{
    extern __shared__ float sm[];
    float* sWih  = sm;                 // [i(6)][j(64)][gate(4)]
    float* sWhh  = sWih + 1536;        // [k(64)][j(64)][gate(4)]
    float* sBias = sWhh + 16384;       // [j(64)][gate(4)]
    float* sH    = sBias + 256;        // [w(8)][k(64)][nb(8)]
    float* sX    = sH + 4096;          // [w(8)][t*6+i(48)][nb(8)]

    const int tid = threadIdx.x;

    for (int idx = tid; idx < 1536; idx += 256) {
        int r = idx / 6, i = idx - r * 6;
        int gate = r >> 6, j = r & 63;
        sWih[(i * 64 + j) * 4 + gate] = Wih[idx];
    }
    for (int idx = tid; idx < 16384; idx += 256) {
        int r = idx >> 6, k = idx & 63;
        int gate = r >> 6, j = r & 63;
        sWhh[(k * 64 + j) * 4 + gate] = Whh[idx];
    }
    if (tid < 256) {
        int gate = tid >> 6, j = tid & 63;
        sBias[j * 4 + gate] = bih[tid] + bhh[tid];
    }
    for (int idx = tid; idx < 4096; idx += 256) sH[idx] = 0.0f;

    const int base = blockIdx.x * BPB;
    for (int idx = tid; idx < BPB * 48; idx += 256) {
        int nbl = idx / 48, rem = idx - nbl * 48;     // nbl = w*8+nb, rem = t*6+i
        int wq = nbl >> 3, nb = nbl & 7;
        sX[wq * 384 + rem * 8 + nb] = x[(base + nbl) * 48 + rem];
    }
    __syncthreads();

    const int w = tid >> 5, lane = tid & 31;
    const float4* W4  = (const float4*)sWhh;
    const float4* Wx4 = (const float4*)sWih;
    const float4* H4  = (const float4*)(sH + w * 512);   // [k][nb8] as 2 float4 per k
    const float4* X4  = (const float4*)(sX + w * 384);   // [rem][nb8] as 2 float4 per rem
    const float4  bj  = ((const float4*)sBias)[lane];
    const float4  bj2 = ((const float4*)sBias)[lane + 32];
    const u64t b_if1 = pk(bj.x, bj.y),  b_go1 = pk(bj.z, bj.w);
    const u64t b_if2 = pk(bj2.x, bj2.y), b_go2 = pk(bj2.z, bj2.w);

    float ca[NB], cb[NB];
#pragma unroll
    for (int nb = 0; nb < NB; nb++) { ca[nb] = cb[nb] = 0.0f; }

    float* gdst = g_h1 + ((size_t)blockIdx.x * WARPS + w) * T_STEPS * 512;

    for (int t = 0; t < T_STEPS; t++) {
        u64t aif1[NB], ago1[NB], aif2[NB], ago2[NB];
#pragma unroll
        for (int nb = 0; nb < NB; nb++) {
            aif1[nb] = b_if1; ago1[nb] = b_go1;
            aif2[nb] = b_if2; ago2[nb] = b_go2;
        }

#pragma unroll
        for (int i = 0; i < 6; i++) K_SLICE(Wx4, X4, i, t * 6 + i);

#pragma unroll 8
        for (int k = 0; k < 64; k++) K_SLICE(W4, H4, k, k);

        __syncwarp();
        float* hrow1 = sH + w * 512 + lane * 8;
        float* hrow2 = sH + w * 512 + (lane + 32) * 8;
        float* grow1 = gdst + t * 512 + lane * 8;
        float* grow2 = gdst + t * 512 + (lane + 32) * 8;
        {
            ACT_AND_STATE(0); ACT_AND_STATE(1); ACT_AND_STATE(2); ACT_AND_STATE(3);
            ACT_AND_STATE(4); ACT_AND_STATE(5); ACT_AND_STATE(6); ACT_AND_STATE(7);
            float4 va0 = {ha_0, ha_1, ha_2, ha_3}, va1 = {ha_4, ha_5, ha_6, ha_7};
            float4 vb0 = {hb_0, hb_1, hb_2, hb_3}, vb1 = {hb_4, hb_5, hb_6, hb_7};
            ((float4*)hrow1)[0] = va0; ((float4*)hrow1)[1] = va1;
            ((float4*)hrow2)[0] = vb0; ((float4*)hrow2)[1] = vb1;
            ((float4*)grow1)[0] = va0; ((float4*)grow1)[1] = va1;
            ((float4*)grow2)[0] = vb0; ((float4*)grow2)[1] = vb1;
        }
        __syncwarp();
    }
}

__global__ void __launch_bounds__(256) lstm_pass2(
    const float* __restrict__ Wih, const float* __restrict__ Whh,
    const float* __restrict__ bih, const float* __restrict__ bhh,
    const float* __restrict__ Wfc, const float* __restrict__ bfc,
    float* __restrict__ out)
{
    extern __shared__ float sm[];
    float* sW    = sm;            // [kk(128)][j(64)][gate(4)]  kk<64: Wih1, kk>=64: Whh1
    float* sBias = sW + 32768;    // [j(64)][gate(4)]
    float* sIn   = sBias + 256;   // [w(8)][kk(128)][nb(8)]  kk<64: layer1 h, kk>=64: layer2 h

    const int tid = threadIdx.x;

    for (int idx = tid; idx < 16384; idx += 256) {
        int r = idx >> 6, k = idx & 63;
        int gate = r >> 6, j = r & 63;
        sW[(k * 64 + j) * 4 + gate]        = Wih[idx];
        sW[((k + 64) * 64 + j) * 4 + gate] = Whh[idx];
    }
    if (tid < 256) {
        int gate = tid >> 6, j = tid & 63;
        sBias[j * 4 + gate] = bih[tid] + bhh[tid];
    }
    for (int idx = tid; idx < 8192; idx += 256) sIn[idx] = 0.0f;
    __syncthreads();

    const int w = tid >> 5, lane = tid & 31;
    const float4* W4 = (const float4*)sW;
    const float4* H4 = (const float4*)(sIn + w * 1024);  // [kk][nb8]
    const float4  bj  = ((const float4*)sBias)[lane];
    const float4  bj2 = ((const float4*)sBias)[lane + 32];
    const u64t b_if1 = pk(bj.x, bj.y),  b_go1 = pk(bj.z, bj.w);
    const u64t b_if2 = pk(bj2.x, bj2.y), b_go2 = pk(bj2.z, bj2.w);
    const float wf1 = Wfc[lane];
    const float wf2 = Wfc[lane + 32];

    float ca[NB], cb[NB];
#pragma unroll
    for (int nb = 0; nb < NB; nb++) { ca[nb] = cb[nb] = 0.0f; }

    const float* gsrc = g_h1 + ((size_t)blockIdx.x * WARPS + w) * T_STEPS * 512;

    float pacc[NB];
#pragma unroll
    for (int nb = 0; nb < NB; nb++) pacc[nb] = 0.0f;

    for (int t = 0; t < T_STEPS; t++) {
        // stage layer-1 h for this step: straight 512-float copy, coalesced
        {
            const float4* src4 = (const float4*)(gsrc + t * 512);
            float4* dst4 = (float4*)(sIn + w * 1024);
#pragma unroll
            for (int q = 0; q < 4; q++) dst4[lane + q * 32] = src4[lane + q * 32];
        }
        __syncwarp();

        u64t aif1[NB], ago1[NB], aif2[NB], ago2[NB];
#pragma unroll
        for (int nb = 0; nb < NB; nb++) {
            aif1[nb] = b_if1; ago1[nb] = b_go1;
            aif2[nb] = b_if2; ago2[nb] = b_go2;
        }

#pragma unroll 8
        for (int k = 0; k < 128; k++) K_SLICE(W4, H4, k, k);

        __syncwarp();
        float* hrow1 = sIn + w * 1024 + (64 + lane) * 8;
        float* hrow2 = sIn + w * 1024 + (64 + lane + 32) * 8;
        {
            ACT_AND_STATE(0); ACT_AND_STATE(1); ACT_AND_STATE(2); ACT_AND_STATE(3);
            ACT_AND_STATE(4); ACT_AND_STATE(5); ACT_AND_STATE(6); ACT_AND_STATE(7);
            float4 va0 = {ha_0, ha_1, ha_2, ha_3}, va1 = {ha_4, ha_5, ha_6, ha_7};
            float4 vb0 = {hb_0, hb_1, hb_2, hb_3}, vb1 = {hb_4, hb_5, hb_6, hb_7};
            ((float4*)hrow1)[0] = va0; ((float4*)hrow1)[1] = va1;
            ((float4*)hrow2)[0] = vb0; ((float4*)hrow2)[1] = vb1;
            if (t == T_STEPS - 1) {
                float ha_arr[8] = {ha_0, ha_1, ha_2, ha_3, ha_4, ha_5, ha_6, ha_7};
                float hb_arr[8] = {hb_0, hb_1, hb_2, hb_3, hb_4, hb_5, hb_6, hb_7};
#pragma unroll
                for (int nb = 0; nb < NB; nb++)
                    pacc[nb] = ha_arr[nb] * wf1 + hb_arr[nb] * wf2;
            }
        }
        __syncwarp();
    }

    // fused FC reduction across lanes (j dimension)
#pragma unroll
    for (int off = 16; off >= 1; off >>= 1) {
#pragma unroll
        for (int nb = 0; nb < NB; nb++)
            pacc[nb] += __shfl_xor_sync(0xffffffffu, pacc[nb], off);
    }
    if (lane == 0) {
        const int base = blockIdx.x * BPB + w * NB;
        float b0 = bfc[0];
#pragma unroll
        for (int nb = 0; nb < NB; nb++) out[base + nb] = pacc[nb] + b0;
    }
}

extern "C" void kernel_launch(void* const* d_in, const int* in_sizes, int n_in,
                              void* d_out, int out_size)
{
    const float* x    = (const float*)d_in[0];
    const float* Wih0 = (const float*)d_in[1];
    const float* Whh0 = (const float*)d_in[2];
    const float* bih0 = (const float*)d_in[3];
    const float* bhh0 = (const float*)d_in[4];
    const float* Wih1 = (const float*)d_in[5];
    const float* Whh1 = (const float*)d_in[6];
    const float* bih1 = (const float*)d_in[7];
    const float* bhh1 = (const float*)d_in[8];
    const float* Wfc  = (const float*)d_in[9];
    const float* bfc  = (const float*)d_in[10];
    float* out = (float*)d_out;

    cudaFuncSetAttribute(lstm_pass1, cudaFuncAttributeMaxDynamicSharedMemorySize, SMEM1_BYTES);
    cudaFuncSetAttribute(lstm_pass2, cudaFuncAttributeMaxDynamicSharedMemorySize, SMEM2_BYTES);

    lstm_pass1<<<NBLK, 256, SMEM1_BYTES>>>(x, Wih0, Whh0, bih0, bhh0);
    lstm_pass2<<<NBLK, 256, SMEM2_BYTES>>>(Wih1, Whh1, bih1, bhh1, Wfc, bfc, out);
}

// round 3
// speedup vs baseline: 1.5489x; 1.1593x over previous
#include <cuda_runtime.h>

#define B_TOTAL 131072
#define T_STEPS 8
#define NB 8
#define WARPS 16
#define THREADS (WARPS * 32)
#define BPB (NB * WARPS)           // 128 batches per block
#define NBLK (B_TOTAL / BPB)       // 1024 blocks

// Layer-1 output scratch, layout [blk][warp][t][k(64)][nb(8)] = 256 MB
__device__ float g_h1[(size_t)NBLK * WARPS * T_STEPS * 64 * NB];

typedef unsigned long long u64t;

__device__ __forceinline__ u64t pk(float x, float y) {
    u64t r; asm("mov.b64 %0, {%1, %2};" : "=l"(r) : "f"(x), "f"(y)); return r;
}
__device__ __forceinline__ void upk(u64t v, float& x, float& y) {
    asm("mov.b64 {%0, %1}, %2;" : "=f"(x), "=f"(y) : "l"(v));
}
__device__ __forceinline__ void fma2(u64t& d, u64t a, u64t b) {
    asm("fma.rn.f32x2 %0, %1, %2, %0;" : "+l"(d) : "l"(a), "l"(b));
}

__device__ __forceinline__ float tanha(float x) {
    float r; asm("tanh.approx.f32 %0, %1;" : "=f"(r) : "f"(x)); return r;
}
__device__ __forceinline__ float sigf(float x) {
    return fmaf(tanha(0.5f * x), 0.5f, 0.5f);
}

// smem float counts
// pass1: sWih 1536 | sWhh 16384 | sBias 256 | sH[16][64][8]=8192 | sX[16][48][8]=6144 -> 32512 (130048 B)
// pass2: sW 32768 | sBias 256 | sIn[16][128][8]=16384 -> 49408 (197632 B)
#define SMEM1_BYTES (32512 * 4)
#define SMEM2_BYTES (49408 * 4)

// one k-slice of the gate GEMM: weights per-lane (2x float4), inputs broadcast (2x float4)
#define K_SLICE(W4PTR, H4PTR, KW, KH)                                          \
    {                                                                           \
        float4 wa = (W4PTR)[(KW) * 64 + lane];                                  \
        float4 wb = (W4PTR)[(KW) * 64 + lane + 32];                             \
        float4 hA = (H4PTR)[(KH) * 2];                                          \
        float4 hB = (H4PTR)[(KH) * 2 + 1];                                      \
        u64t wif1 = pk(wa.x, wa.y), wgo1 = pk(wa.z, wa.w);                      \
        u64t wif2 = pk(wb.x, wb.y), wgo2 = pk(wb.z, wb.w);                      \
        float hv[8] = {hA.x, hA.y, hA.z, hA.w, hB.x, hB.y, hB.z, hB.w};         \
        _Pragma("unroll")                                                       \
        for (int nb = 0; nb < NB; nb++) {                                       \
            u64t vv = pk(hv[nb], hv[nb]);                                       \
            fma2(aif1[nb], vv, wif1);                                           \
            fma2(ago1[nb], vv, wgo1);                                           \
            fma2(aif2[nb], vv, wif2);                                           \
            fma2(ago2[nb], vv, wgo2);                                           \
        }                                                                       \
    }

#define ACT_AND_STATE(nb)                                                       \
    float ha_##nb, hb_##nb;                                                     \
    {                                                                           \
        float gi, gf, gg, go;                                                   \
        upk(aif1[nb], gi, gf); upk(ago1[nb], gg, go);                           \
        float i1 = sigf(gi), f1 = sigf(gf), g1 = tanha(gg), o1 = sigf(go);      \
        ca[nb] = f1 * ca[nb] + i1 * g1;                                         \
        ha_##nb = o1 * tanha(ca[nb]);                                           \
        upk(aif2[nb], gi, gf); upk(ago2[nb], gg, go);                           \
        float i2 = sigf(gi), f2 = sigf(gf), g2 = tanha(gg), o2 = sigf(go);      \
        cb[nb] = f2 * cb[nb] + i2 * g2;                                         \
        hb_##nb = o2 * tanha(cb[nb]);                                           \
    }

__global__ void __launch_bounds__(THREADS) lstm_pass1(
    const float* __restrict__ x,
    const float* __restrict__ Wih, const float* __restrict__ Whh,
    const float* __restrict__ bih, const float* __restrict__ bhh)
{
    extern __shared__ float sm[];
    float* sWih  = sm;                 // [i(6)][j(64)][gate(4)]
    float* sWhh  = sWih + 1536;        // [k(64)][j(64)][gate(4)]
    float* sBias = sWhh + 16384;       // [j(64)][gate(4)]
    float* sH    = sBias + 256;        // [w(16)][k(64)][nb(8)]
    float* sX    = sH + WARPS * 512;   // [w(16)][t*6+i(48)][nb(8)]

    const int tid = threadIdx.x;

    for (int idx = tid; idx < 1536; idx += THREADS) {
        int r = idx / 6, i = idx - r * 6;
        int gate = r >> 6, j = r & 63;
        sWih[(i * 64 + j) * 4 + gate] = Wih[idx];
    }
    for (int idx = tid; idx < 16384; idx += THREADS) {
        int r = idx >> 6, k = idx & 63;
        int gate = r >> 6, j = r & 63;
        sWhh[(k * 64 + j) * 4 + gate] = Whh[idx];
    }
    if (tid < 256) {
        int gate = tid >> 6, j = tid & 63;
        sBias[j * 4 + gate] = bih[tid] + bhh[tid];
    }
    for (int idx = tid; idx < WARPS * 512; idx += THREADS) sH[idx] = 0.0f;

    const int base = blockIdx.x * BPB;
    for (int idx = tid; idx < BPB * 48; idx += THREADS) {
        int nbl = idx / 48, rem = idx - nbl * 48;     // nbl = w*8+nb, rem = t*6+i
        int wq = nbl >> 3, nb = nbl & 7;
        sX[wq * 384 + rem * 8 + nb] = x[(base + nbl) * 48 + rem];
    }
    __syncthreads();

    const int w = tid >> 5, lane = tid & 31;
    const float4* W4  = (const float4*)sWhh;
    const float4* Wx4 = (const float4*)sWih;
    const float4* H4  = (const float4*)(sH + w * 512);   // [k][nb8] as 2 float4 per k
    const float4* X4  = (const float4*)(sX + w * 384);   // [rem][nb8] as 2 float4 per rem
    const float4  bj  = ((const float4*)sBias)[lane];
    const float4  bj2 = ((const float4*)sBias)[lane + 32];
    const u64t b_if1 = pk(bj.x, bj.y),  b_go1 = pk(bj.z, bj.w);
    const u64t b_if2 = pk(bj2.x, bj2.y), b_go2 = pk(bj2.z, bj2.w);

    float ca[NB], cb[NB];
#pragma unroll
    for (int nb = 0; nb < NB; nb++) { ca[nb] = cb[nb] = 0.0f; }

    float* gdst = g_h1 + ((size_t)blockIdx.x * WARPS + w) * T_STEPS * 512;

    for (int t = 0; t < T_STEPS; t++) {
        u64t aif1[NB], ago1[NB], aif2[NB], ago2[NB];
#pragma unroll
        for (int nb = 0; nb < NB; nb++) {
            aif1[nb] = b_if1; ago1[nb] = b_go1;
            aif2[nb] = b_if2; ago2[nb] = b_go2;
        }

#pragma unroll
        for (int i = 0; i < 6; i++) K_SLICE(Wx4, X4, i, t * 6 + i);

#pragma unroll 8
        for (int k = 0; k < 64; k++) K_SLICE(W4, H4, k, k);

        __syncwarp();
        float* hrow1 = sH + w * 512 + lane * 8;
        float* hrow2 = sH + w * 512 + (lane + 32) * 8;
        float* grow1 = gdst + t * 512 + lane * 8;
        float* grow2 = gdst + t * 512 + (lane + 32) * 8;
        {
            ACT_AND_STATE(0); ACT_AND_STATE(1); ACT_AND_STATE(2); ACT_AND_STATE(3);
            ACT_AND_STATE(4); ACT_AND_STATE(5); ACT_AND_STATE(6); ACT_AND_STATE(7);
            float4 va0 = {ha_0, ha_1, ha_2, ha_3}, va1 = {ha_4, ha_5, ha_6, ha_7};
            float4 vb0 = {hb_0, hb_1, hb_2, hb_3}, vb1 = {hb_4, hb_5, hb_6, hb_7};
            ((float4*)hrow1)[0] = va0; ((float4*)hrow1)[1] = va1;
            ((float4*)hrow2)[0] = vb0; ((float4*)hrow2)[1] = vb1;
            ((float4*)grow1)[0] = va0; ((float4*)grow1)[1] = va1;
            ((float4*)grow2)[0] = vb0; ((float4*)grow2)[1] = vb1;
        }
        __syncwarp();
    }
}

__global__ void __launch_bounds__(THREADS) lstm_pass2(
    const float* __restrict__ Wih, const float* __restrict__ Whh,
    const float* __restrict__ bih, const float* __restrict__ bhh,
    const float* __restrict__ Wfc, const float* __restrict__ bfc,
    float* __restrict__ out)
{
    extern __shared__ float sm[];
    float* sW    = sm;            // [kk(128)][j(64)][gate(4)]  kk<64: Wih1, kk>=64: Whh1
    float* sBias = sW + 32768;    // [j(64)][gate(4)]
    float* sIn   = sBias + 256;   // [w(16)][kk(128)][nb(8)]  kk<64: layer1 h, kk>=64: layer2 h

    const int tid = threadIdx.x;

    for (int idx = tid; idx < 16384; idx += THREADS) {
        int r = idx >> 6, k = idx & 63;
        int gate = r >> 6, j = r & 63;
        sW[(k * 64 + j) * 4 + gate]        = Wih[idx];
        sW[((k + 64) * 64 + j) * 4 + gate] = Whh[idx];
    }
    if (tid < 256) {
        int gate = tid >> 6, j = tid & 63;
        sBias[j * 4 + gate] = bih[tid] + bhh[tid];
    }
    for (int idx = tid; idx < WARPS * 1024; idx += THREADS) sIn[idx] = 0.0f;
    __syncthreads();

    const int w = tid >> 5, lane = tid & 31;
    const float4* W4 = (const float4*)sW;
    const float4* H4 = (const float4*)(sIn + w * 1024);  // [kk][nb8]
    const float4  bj  = ((const float4*)sBias)[lane];
    const float4  bj2 = ((const float4*)sBias)[lane + 32];
    const u64t b_if1 = pk(bj.x, bj.y),  b_go1 = pk(bj.z, bj.w);
    const u64t b_if2 = pk(bj2.x, bj2.y), b_go2 = pk(bj2.z, bj2.w);
    const float wf1 = Wfc[lane];
    const float wf2 = Wfc[lane + 32];

    float ca[NB], cb[NB];
#pragma unroll
    for (int nb = 0; nb < NB; nb++) { ca[nb] = cb[nb] = 0.0f; }

    const float* gsrc = g_h1 + ((size_t)blockIdx.x * WARPS + w) * T_STEPS * 512;

    float pacc[NB];
#pragma unroll
    for (int nb = 0; nb < NB; nb++) pacc[nb] = 0.0f;

    for (int t = 0; t < T_STEPS; t++) {
        // stage layer-1 h for this step: straight 512-float copy, coalesced
        {
            const float4* src4 = (const float4*)(gsrc + t * 512);
            float4* dst4 = (float4*)(sIn + w * 1024);
#pragma unroll
            for (int q = 0; q < 4; q++) dst4[lane + q * 32] = src4[lane + q * 32];
        }
        __syncwarp();

        u64t aif1[NB], ago1[NB], aif2[NB], ago2[NB];
#pragma unroll
        for (int nb = 0; nb < NB; nb++) {
            aif1[nb] = b_if1; ago1[nb] = b_go1;
            aif2[nb] = b_if2; ago2[nb] = b_go2;
        }

#pragma unroll 8
        for (int k = 0; k < 128; k++) K_SLICE(W4, H4, k, k);

        __syncwarp();
        float* hrow1 = sIn + w * 1024 + (64 + lane) * 8;
        float* hrow2 = sIn + w * 1024 + (64 + lane + 32) * 8;
        {
            ACT_AND_STATE(0); ACT_AND_STATE(1); ACT_AND_STATE(2); ACT_AND_STATE(3);
            ACT_AND_STATE(4); ACT_AND_STATE(5); ACT_AND_STATE(6); ACT_AND_STATE(7);
            float4 va0 = {ha_0, ha_1, ha_2, ha_3}, va1 = {ha_4, ha_5, ha_6, ha_7};
            float4 vb0 = {hb_0, hb_1, hb_2, hb_3}, vb1 = {hb_4, hb_5, hb_6, hb_7};
            ((float4*)hrow1)[0] = va0; ((float4*)hrow1)[1] = va1;
            ((float4*)hrow2)[0] = vb0; ((float4*)hrow2)[1] = vb1;
            if (t == T_STEPS - 1) {
                float ha_arr[8] = {ha_0, ha_1, ha_2, ha_3, ha_4, ha_5, ha_6, ha_7};
                float hb_arr[8] = {hb_0, hb_1, hb_2, hb_3, hb_4, hb_5, hb_6, hb_7};
#pragma unroll
                for (int nb = 0; nb < NB; nb++)
                    pacc[nb] = ha_arr[nb] * wf1 + hb_arr[nb] * wf2;
            }
        }
        __syncwarp();
    }

    // fused FC reduction across lanes (j dimension)
#pragma unroll
    for (int off = 16; off >= 1; off >>= 1) {
#pragma unroll
        for (int nb = 0; nb < NB; nb++)
            pacc[nb] += __shfl_xor_sync(0xffffffffu, pacc[nb], off);
    }
    if (lane == 0) {
        const int base = blockIdx.x * BPB + w * NB;
        float b0 = bfc[0];
#pragma unroll
        for (int nb = 0; nb < NB; nb++) out[base + nb] = pacc[nb] + b0;
    }
}

extern "C" void kernel_launch(void* const* d_in, const int* in_sizes, int n_in,
                              void* d_out, int out_size)
{
    const float* x    = (const float*)d_in[0];
    const float* Wih0 = (const float*)d_in[1];
    const float* Whh0 = (const float*)d_in[2];
    const float* bih0 = (const float*)d_in[3];
    const float* bhh0 = (const float*)d_in[4];
    const float* Wih1 = (const float*)d_in[5];
    const float* Whh1 = (const float*)d_in[6];
    const float* bih1 = (const float*)d_in[7];
    const float* bhh1 = (const float*)d_in[8];
    const float* Wfc  = (const float*)d_in[9];
    const float* bfc  = (const float*)d_in[10];
    float* out = (float*)d_out;

    cudaFuncSetAttribute(lstm_pass1, cudaFuncAttributeMaxDynamicSharedMemorySize, SMEM1_BYTES);
    cudaFuncSetAttribute(lstm_pass2, cudaFuncAttributeMaxDynamicSharedMemorySize, SMEM2_BYTES);

    lstm_pass1<<<NBLK, THREADS, SMEM1_BYTES>>>(x, Wih0, Whh0, bih0, bhh0);
    lstm_pass2<<<NBLK, THREADS, SMEM2_BYTES>>>(Wih1, Whh1, bih1, bhh1, Wfc, bfc, out);
}